// round 9
// baseline (speedup 1.0000x reference)
#include <cuda_runtime.h>

#define INPUT_SIZE     32768
#define NUM_COLS       4096
#define NUM_ACTIVE     82
#define THREADS        256
#define ROWS_PER_BLOCK 4
#define NBLOCKS        (NUM_COLS / ROWS_PER_BLOCK)   // 1024
#define COMPACT_BLOCKS 128
#define NUM_LINES      (INPUT_SIZE / 32)             // 1024 lines of 32 floats
#define HIST_BINS      2048

// Scratch (allocation-free rule). Zero-initialized at module load; flags reset
// by the elected block at the end of each call -> graph replays deterministic.
// g_bitmask is fully rewritten every call before any read.
__device__ volatile int g_ready;
__device__ int          g_done;
__device__ unsigned     g_bitmask[NUM_LINES];
__device__ float        g_boosted[NUM_COLS];

// ---------------------------------------------------------------------------
// ONE fused kernel:
//   Phase A (blocks 0..127): build the 32768-bit input mask, one ballot word
//     per 32-float line (deterministic: word w written by exactly one warp).
//   Phase B (all blocks): spin on flag, stage bitmask in SMEM, build the
//     SORTED list of touched lines, then sweep touched lines whole:
//     8 lanes x float4 per 128B line, 4 rows per block (4 LDG.128 streams
//     per lane), accumulate elements selected by mask bits. All requests are
//     coalesced, fully-consumed 128B lines -> streaming-friendly DRAM pattern
//     at the same touched-line traffic floor as the scattered gather.
//   Phase C (last-finishing block): 2048-bin histogram top-k over the exact
//     integer overlaps; stable tie-break by column index == jax.lax.top_k
//     order; writes both output segments; resets flags.
// ---------------------------------------------------------------------------
__global__ __launch_bounds__(THREADS)
void fused_kernel(const float* __restrict__ in,
                  const float* __restrict__ conn,
                  const float* __restrict__ boost,
                  float* __restrict__ out) {
    __shared__ int   buf[2048];          // B: [0,1024)=bitmask, [1024,2048)=line list
    __shared__ int   s_nl;               //    (C: reused as 2048-bin histogram)
    __shared__ int   wsum[8];
    __shared__ float wred[32];
    __shared__ int   s_elected;
    __shared__ int   sT, sR;
    __shared__ int   scan_tmp[THREADS];

    const int tid  = threadIdx.x;
    const int bid  = blockIdx.x;
    const int lane = tid & 31;
    const int warp = tid >> 5;

    // ================= Phase A: bitmask build (blocks 0..127) =============
    if (bid < COMPACT_BLOCKS) {
        const int idx = bid * 256 + tid;             // one element per thread
        const bool on = (in[idx] != 0.0f);
        const unsigned m = __ballot_sync(0xffffffffu, on);
        if (lane == 0) g_bitmask[bid * 8 + warp] = m; // word per 32-elem line
        __threadfence();
        __syncthreads();                              // all warps published
        if (tid == 0) atomicAdd((int*)&g_ready, 1);
    }

    // ================= Wait for bitmask =================
    if (tid == 0) {
        while (*(volatile int*)&g_ready < COMPACT_BLOCKS) __nanosleep(64);
        __threadfence();
    }
    __syncthreads();

    // ================= Phase B: stage bitmask + build sorted line list ====
    unsigned* sbits = reinterpret_cast<unsigned*>(buf);
    int*      slist = buf + NUM_LINES;

    for (int w = tid; w < NUM_LINES; w += THREADS)
        sbits[w] = __ldcg(&g_bitmask[w]);
    __syncthreads();

    {   // thread t owns words [4t, 4t+4) -> list stays globally sorted
        int myl[4]; int cnt = 0;
#pragma unroll
        for (int i = 0; i < 4; i++) {
            int w = tid * 4 + i;
            if (sbits[w] != 0u) myl[cnt++] = w;
        }
        int x = cnt;
#pragma unroll
        for (int d = 1; d < 32; d <<= 1) {
            int y = __shfl_up_sync(0xffffffffu, x, d);
            if (lane >= d) x += y;                   // inclusive warp scan
        }
        if (lane == 31) wsum[warp] = x;
        __syncthreads();
        if (tid == 0) {
            int acc = 0;
#pragma unroll
            for (int w = 0; w < 8; w++) { int c = wsum[w]; wsum[w] = acc; acc += c; }
            s_nl = acc;
        }
        __syncthreads();
        int off = wsum[warp] + (x - cnt);
        for (int i = 0; i < cnt; i++) slist[off + i] = myl[i];
    }
    __syncthreads();
    const int nL = s_nl;

    // ================= Phase B: line-dense gather, 4 rows ==================
    const int r = bid * ROWS_PER_BLOCK;
    const float* __restrict__ row0 = conn + (size_t)r * INPUT_SIZE;
    const float* __restrict__ row1 = row0 + INPUT_SIZE;
    const float* __restrict__ row2 = row1 + INPUT_SIZE;
    const float* __restrict__ row3 = row2 + INPUT_SIZE;

    float s0 = 0.f, s1 = 0.f, s2 = 0.f, s3 = 0.f;
    const int sub = lane & 7;                        // 8 lanes per line
    for (int base = warp * 4; base < nL; base += 32) {
        const int li = base + (lane >> 3);
        unsigned bits = 0u;
        float4 f0, f1, f2, f3;
        if (li < nL) {
            const int line = slist[li];
            const int off  = line * 32 + sub * 4;
            f0 = __ldcs(reinterpret_cast<const float4*>(row0 + off));
            f1 = __ldcs(reinterpret_cast<const float4*>(row1 + off));
            f2 = __ldcs(reinterpret_cast<const float4*>(row2 + off));
            f3 = __ldcs(reinterpret_cast<const float4*>(row3 + off));
            bits = (sbits[line] >> (sub * 4)) & 0xFu;
        }
        if (bits & 1u) { s0 += f0.x; s1 += f1.x; s2 += f2.x; s3 += f3.x; }
        if (bits & 2u) { s0 += f0.y; s1 += f1.y; s2 += f2.y; s3 += f3.y; }
        if (bits & 4u) { s0 += f0.z; s1 += f1.z; s2 += f2.z; s3 += f3.z; }
        if (bits & 8u) { s0 += f0.w; s1 += f1.w; s2 += f2.w; s3 += f3.w; }
    }

    // ---- Block reduce all four rows ----
#pragma unroll
    for (int dd = 16; dd; dd >>= 1) {
        s0 += __shfl_down_sync(0xffffffffu, s0, dd);
        s1 += __shfl_down_sync(0xffffffffu, s1, dd);
        s2 += __shfl_down_sync(0xffffffffu, s2, dd);
        s3 += __shfl_down_sync(0xffffffffu, s3, dd);
    }
    if (lane == 0) {
        wred[warp]      = s0;  wred[8 + warp]  = s1;
        wred[16 + warp] = s2;  wred[24 + warp] = s3;
    }
    __syncthreads();

    if (tid == 0) {
        float t0 = 0.f, t1 = 0.f, t2 = 0.f, t3 = 0.f;
#pragma unroll
        for (int w = 0; w < 8; w++) {
            t0 += wred[w]; t1 += wred[8 + w]; t2 += wred[16 + w]; t3 += wred[24 + w];
        }
        g_boosted[r]     = t0 * __ldg(&boost[r]);
        g_boosted[r + 1] = t1 * __ldg(&boost[r + 1]);
        g_boosted[r + 2] = t2 * __ldg(&boost[r + 2]);
        g_boosted[r + 3] = t3 * __ldg(&boost[r + 3]);
        __threadfence();
        int ticket = atomicAdd(&g_done, 1);
        s_elected = (ticket == NBLOCKS - 1) ? 1 : 0;
    }
    __syncthreads();

    // ================= Phase C: top-k (elected block only) =================
    if (s_elected) {
        if (tid == 0) __threadfence();   // acquire: see all g_boosted writes
        __syncthreads();

        // Single load of my 16 contiguous columns (L2 path, coalesced).
        const int cbase = tid * 16;
        float va[16];
        const float4* gb4 = reinterpret_cast<const float4*>(g_boosted);
#pragma unroll
        for (int i = 0; i < 4; i++) {
            float4 f = __ldcg(&gb4[tid * 4 + i]);
            va[4*i+0] = f.x; va[4*i+1] = f.y;
            va[4*i+2] = f.z; va[4*i+3] = f.w;
        }

        // Zero histogram (reuse buf: 2048 bins, 8 per thread), then populate.
#pragma unroll
        for (int i = 0; i < 8; i++) buf[tid * 8 + i] = 0;
        __syncthreads();
#pragma unroll
        for (int i = 0; i < 16; i++) {
            int t = (int)va[i];                       // exact small integers
            if (t >= HIST_BINS) t = HIST_BINS - 1;
            atomicAdd(&buf[t], 1);
        }
        __syncthreads();

        // Per-thread bin-sum over owned bins [8*tid, 8*tid+8).
        int s = 0;
#pragma unroll
        for (int i = 0; i < 8; i++) s += buf[tid * 8 + i];

        // Suffix scan: above = sum of bins owned by higher tids.
        scan_tmp[255 - tid] = s;
        __syncthreads();
        {
            int x = scan_tmp[tid];
#pragma unroll
            for (int d = 1; d < 32; d <<= 1) {
                int y = __shfl_up_sync(0xffffffffu, x, d);
                if (lane >= d) x += y;                // inclusive warp scan
            }
            if (lane == 31) wsum[warp] = x;
            __syncthreads();
            if (tid == 0) {
                int acc = 0;
#pragma unroll
                for (int w = 0; w < 8; w++) { int c = wsum[w]; wsum[w] = acc; acc += c; }
            }
            __syncthreads();
            int excl = wsum[warp] + x - scan_tmp[tid];
            __syncthreads();
            scan_tmp[255 - tid] = excl;
        }
        __syncthreads();
        const int above = scan_tmp[tid];

        // Locate threshold bin T (unique: GE >= K > GT) and residue R.
        {
            int running = above;
            for (int bin = tid * 8 + 7; bin >= tid * 8; --bin) {
                int cb = buf[bin];
                if (running < NUM_ACTIVE && running + cb >= NUM_ACTIVE) {
                    sT = bin;
                    sR = NUM_ACTIVE - running;        // ties to take, index order
                }
                running += cb;
            }
        }
        __syncthreads();
        const int T = sT, R = sR;

        // Stable tie prefix: ascending exclusive scan of per-thread eq counts.
        int eq = 0;
#pragma unroll
        for (int i = 0; i < 16; i++) {
            int t = (int)va[i];
            if (t >= HIST_BINS) t = HIST_BINS - 1;
            eq += (t == T) ? 1 : 0;
        }
        int run;
        {
            int x = eq;
#pragma unroll
            for (int d = 1; d < 32; d <<= 1) {
                int y = __shfl_up_sync(0xffffffffu, x, d);
                if (lane >= d) x += y;
            }
            if (lane == 31) wsum[warp] = x;
            __syncthreads();
            if (tid == 0) {
                int acc = 0;
#pragma unroll
                for (int w = 0; w < 8; w++) { int c = wsum[w]; wsum[w] = acc; acc += c; }
            }
            __syncthreads();
            run = wsum[warp] + x - eq;                // exclusive prefix
        }

        // Decide winners, write both output segments (float4 stores).
        {
            float mk[16], mv[16];
#pragma unroll
            for (int i = 0; i < 16; i++) {
                int t = (int)va[i];
                if (t >= HIST_BINS) t = HIST_BINS - 1;
                bool win;
                if (t > T)       win = true;
                else if (t == T) { win = (run < R); run++; }
                else             win = false;
                mk[i] = win ? 1.0f  : 0.0f;
                mv[i] = win ? va[i] : 0.0f;
            }
            float4* o0 = reinterpret_cast<float4*>(out + cbase);
            float4* o1 = reinterpret_cast<float4*>(out + NUM_COLS + cbase);
#pragma unroll
            for (int i = 0; i < 4; i++) {
                o0[i] = make_float4(mk[4*i], mk[4*i+1], mk[4*i+2], mk[4*i+3]);
                o1[i] = make_float4(mv[4*i], mv[4*i+1], mv[4*i+2], mv[4*i+3]);
            }
        }

        // Reset flags for the next graph replay.
        if (tid == 0) { g_ready = 0; g_done = 0; }
    }
}

// ---------------------------------------------------------------------------
extern "C" void kernel_launch(void* const* d_in, const int* in_sizes, int n_in,
                              void* d_out, int out_size) {
    const float* inp   = nullptr;
    const float* conn  = nullptr;
    const float* boost = nullptr;
    for (int i = 0; i < n_in; i++) {
        if (in_sizes[i] == INPUT_SIZE)      inp   = (const float*)d_in[i];
        else if (in_sizes[i] == NUM_COLS)   boost = (const float*)d_in[i];
        else                                conn  = (const float*)d_in[i];
    }
    float* out = (float*)d_out;
    (void)out_size; (void)n_in;

    fused_kernel<<<NBLOCKS, THREADS>>>(inp, conn, boost, out);
}